// round 4
// baseline (speedup 1.0000x reference)
#include <cuda_runtime.h>
#include <cuda_bf16.h>

// Problem: DotProductAttention_83476984365340
// softmax over singleton axis == 1.0 -> output = values.sum(axis=1).
// Pure HBM-bound column sum of values [32, 4096, 1024] f32 (512 MiB read).
//
// R1/R3 (512 CTAs): ncu 81.9-82.4us, DRAM ~83%, 6.6 TB/s.
// R2 (1024 CTAs + ldcs): regression.
// R4 theory: 512 CTAs = 3.46 waves -> starved 68-CTA tail wave costs ~2us.
//   Fix: grid = 37 x 32 = 1184 CTAs = EXACTLY 8 waves of 148 SMs.
//   Each CTA covers rows [c*4096/37, (c+1)*4096/37) of one batch b (110/111 rows).

#define B_DIM 32
#define T_DIM 4096
#define D_DIM 1024
#define CHUNKS_PER_B 37
#define THREADS 256                      // 256 threads * float4 = 1024 = D
#define BATCH 8

__global__ __launch_bounds__(THREADS, 8)
void values_colsum_kernel(const float* __restrict__ values, float* __restrict__ out)
{
    const int b  = blockIdx.y;                 // 0..31
    const int c  = blockIdx.x;                 // 0..36
    const int d4 = threadIdx.x;                // float4 lane within row (0..255)

    // Balanced split of 4096 rows into 37 chunks (110 or 111 rows each).
    const int t0 = (c * T_DIM) / CHUNKS_PER_B;
    const int t1 = ((c + 1) * T_DIM) / CHUNKS_PER_B;
    const int nrows = t1 - t0;

    const float4* __restrict__ p =
        reinterpret_cast<const float4*>(values) +
        (size_t)b * T_DIM * (D_DIM / 4) +
        (size_t)t0 * (D_DIM / 4) +
        d4;

    float4 acc0 = make_float4(0.f, 0.f, 0.f, 0.f);
    float4 acc1 = make_float4(0.f, 0.f, 0.f, 0.f);

    const int nbatched = nrows & ~(BATCH - 1);

    for (int it = 0; it < nbatched; it += BATCH) {
        // Front-batch BATCH independent 128-bit loads.
        float4 v[BATCH];
        #pragma unroll
        for (int k = 0; k < BATCH; ++k)
            v[k] = p[(size_t)k * (D_DIM / 4)];
        p += (size_t)BATCH * (D_DIM / 4);

        #pragma unroll
        for (int k = 0; k < BATCH; k += 2) {
            acc0.x += v[k].x;   acc0.y += v[k].y;
            acc0.z += v[k].z;   acc0.w += v[k].w;
            acc1.x += v[k+1].x; acc1.y += v[k+1].y;
            acc1.z += v[k+1].z; acc1.w += v[k+1].w;
        }
    }

    // Remainder rows (nrows % 8 = 6 or 7).
    for (int r = nbatched; r < nrows; ++r) {
        float4 v = *p;
        p += (D_DIM / 4);
        acc0.x += v.x; acc0.y += v.y; acc0.z += v.z; acc0.w += v.w;
    }

    acc0.x += acc1.x; acc0.y += acc1.y; acc0.z += acc1.z; acc0.w += acc1.w;

    float* o = out + (size_t)b * D_DIM + d4 * 4;
    atomicAdd(o + 0, acc0.x);
    atomicAdd(o + 1, acc0.y);
    atomicAdd(o + 2, acc0.z);
    atomicAdd(o + 3, acc0.w);
}

extern "C" void kernel_launch(void* const* d_in, const int* in_sizes, int n_in,
                              void* d_out, int out_size)
{
    // Input order per reference setup_inputs(): query, keys, values, W
    const float* values = (const float*)d_in[2];
    float* out = (float*)d_out;

    cudaMemsetAsync(out, 0, (size_t)out_size * sizeof(float));

    dim3 grid(CHUNKS_PER_B, B_DIM);
    values_colsum_kernel<<<grid, THREADS>>>(values, out);
}

// round 5
// speedup vs baseline: 1.0820x; 1.0820x over previous
#include <cuda_runtime.h>
#include <cuda_bf16.h>

// Problem: DotProductAttention_83476984365340
// softmax over singleton axis == 1.0 -> output = values.sum(axis=1).
// Pure HBM-bound column sum of values [32, 4096, 1024] f32 (512 MiB read).
//
// History (all single-wave, resident simultaneously):
//   512 CTAs (3.5/SM): 81.9-82.4us ncu, 6.61 TB/s   <- best
//  1024 CTAs (6.9/SM): 84.6us,           6.38 TB/s
//  1184 CTAs (8.0/SM): 86.1us,           6.31 TB/s
// Pattern: fewer concurrent streams/SM => better DRAM efficiency.
// R5: 256 CTAs (1.7/SM), 2 MiB contiguous stream each, BATCH=16 to keep
//     ~4.2 MB in flight (>= 2x latency-BW product). 512 rows = 32x16 exact.

#define B_DIM 32
#define T_DIM 4096
#define D_DIM 1024
#define CHUNKS_PER_B 8
#define T_PER_CHUNK (T_DIM / CHUNKS_PER_B)  // 512
#define THREADS 256                          // 256 threads * float4 = 1024 = D
#define BATCH 16

__global__ __launch_bounds__(THREADS, 2)
void values_colsum_kernel(const float* __restrict__ values, float* __restrict__ out)
{
    const int b  = blockIdx.y;                 // 0..31
    const int c  = blockIdx.x;                 // 0..7
    const int d4 = threadIdx.x;                // float4 lane within row (0..255)

    const float4* __restrict__ p =
        reinterpret_cast<const float4*>(values) +
        (size_t)b * T_DIM * (D_DIM / 4) +
        (size_t)c * T_PER_CHUNK * (D_DIM / 4) +
        d4;

    float4 acc0 = make_float4(0.f, 0.f, 0.f, 0.f);
    float4 acc1 = make_float4(0.f, 0.f, 0.f, 0.f);

    for (int it = 0; it < T_PER_CHUNK / BATCH; ++it) {
        // Front-batch BATCH independent 128-bit loads -> deep MLP.
        float4 v[BATCH];
        #pragma unroll
        for (int k = 0; k < BATCH; ++k)
            v[k] = p[(size_t)k * (D_DIM / 4)];
        p += (size_t)BATCH * (D_DIM / 4);

        #pragma unroll
        for (int k = 0; k < BATCH; k += 2) {
            acc0.x += v[k].x;   acc0.y += v[k].y;
            acc0.z += v[k].z;   acc0.w += v[k].w;
            acc1.x += v[k+1].x; acc1.y += v[k+1].y;
            acc1.z += v[k+1].z; acc1.w += v[k+1].w;
        }
    }

    acc0.x += acc1.x; acc0.y += acc1.y; acc0.z += acc1.z; acc0.w += acc1.w;

    float* o = out + (size_t)b * D_DIM + d4 * 4;
    atomicAdd(o + 0, acc0.x);
    atomicAdd(o + 1, acc0.y);
    atomicAdd(o + 2, acc0.z);
    atomicAdd(o + 3, acc0.w);
}

extern "C" void kernel_launch(void* const* d_in, const int* in_sizes, int n_in,
                              void* d_out, int out_size)
{
    // Input order per reference setup_inputs(): query, keys, values, W
    const float* values = (const float*)d_in[2];
    float* out = (float*)d_out;

    cudaMemsetAsync(out, 0, (size_t)out_size * sizeof(float));

    dim3 grid(CHUNKS_PER_B, B_DIM);
    values_colsum_kernel<<<grid, THREADS>>>(values, out);
}